// round 7
// baseline (speedup 1.0000x reference)
#include <cuda_runtime.h>
#include <cstdint>

// ---------------------------------------------------------------------------
// GCN decoder: 4 x (GCNConv [+ReLU] [+upsample x2 folded into indexing])
// Per layer:
//   memset(cnt)=0
//   build:   p = atomicAdd(cnt[dst]); adj[dst*64+p] = src        (CSR-ish)
//   rsqrt:   dinv = rsqrt(cnt + 1)                               (self loop)
//   GEMM:    hraw = X @ W     on RAW rows (pre-upsample)
//   agg:     warp per dst: acc = sum_e dinv[src]*hraw[src>>sh] + dinv[d]*hraw[d>>sh]
//            out = dinv[d]*acc + b [, relu]     (no atomics, registers only)
// ---------------------------------------------------------------------------

#define MAXN 200000
#define MAXF 6400000
#define CAP  64

__device__ __align__(256) int   g_cnt[MAXN];
__device__ __align__(256) float g_dinv[MAXN];
__device__ __align__(256) int   g_adj[MAXN * CAP];
__device__ __align__(256) float g_hraw[MAXF];
__device__ __align__(256) float g_p1  [MAXF];   // ping
__device__ __align__(256) float g_p2  [MAXF];   // pong

// ---------------- adjacency build + dinv ----------------

__global__ void k_build(const int* __restrict__ src,
                        const int* __restrict__ dst,
                        int* __restrict__ cnt,
                        int* __restrict__ adj, int E) {
    int i = blockIdx.x * blockDim.x + threadIdx.x;
    if (i < E) {
        int d = dst[i];
        int p = atomicAdd(&cnt[d], 1);
        if (p < CAP) adj[d * CAP + p] = src[i];
    }
}

__global__ void k_rsqrt(const int* __restrict__ cnt,
                        float* __restrict__ dinv, int M) {
    int i = blockIdx.x * blockDim.x + threadIdx.x;
    if (i < M) dinv[i] = rsqrtf((float)cnt[i] + 1.0f);
}

// ---------------- tiled GEMM: hraw = X @ W ----------------------------------
// BM=128, BN=64, BK=16, 256 threads, 8x4 microtile per thread.

__global__ __launch_bounds__(256) void k_gemm_tiled(
        const float* __restrict__ X,
        const float* __restrict__ W,
        float* __restrict__ hraw,
        int Mr, int K, int F) {
    __shared__ float As[16][128];   // transposed: As[k][row]
    __shared__ float Bs[16][64];

    const int tid = threadIdx.x;
    const int tx  = tid & 15;
    const int ty  = tid >> 4;
    const int row0 = blockIdx.y * 128;
    const int col0 = blockIdx.x * 64;

    const int brow = tid >> 4;
    const int bc   = (tid & 15) * 4;

    float c[8][4] = {};
    float a[8], b[4];

    for (int k0 = 0; k0 < K; k0 += 16) {
        #pragma unroll
        for (int li = 0; li < 2; li++) {
            int i = tid + li * 256;
            int r  = i >> 2;
            int kc = (i & 3) * 4;
            int grow = row0 + r;
            float4 v = make_float4(0.f, 0.f, 0.f, 0.f);
            if (grow < Mr)
                v = *reinterpret_cast<const float4*>(
                    X + (size_t)grow * K + k0 + kc);
            As[kc + 0][r] = v.x;
            As[kc + 1][r] = v.y;
            As[kc + 2][r] = v.z;
            As[kc + 3][r] = v.w;
        }
        *reinterpret_cast<float4*>(&Bs[brow][bc]) =
            *reinterpret_cast<const float4*>(W + (size_t)(k0 + brow) * F + col0 + bc);

        __syncthreads();

        #pragma unroll
        for (int kk = 0; kk < 16; kk++) {
            *reinterpret_cast<float4*>(&a[0]) = *reinterpret_cast<float4*>(&As[kk][ty * 8]);
            *reinterpret_cast<float4*>(&a[4]) = *reinterpret_cast<float4*>(&As[kk][ty * 8 + 4]);
            *reinterpret_cast<float4*>(&b[0]) = *reinterpret_cast<float4*>(&Bs[kk][tx * 4]);
            #pragma unroll
            for (int i = 0; i < 8; i++) {
                c[i][0] += a[i] * b[0];
                c[i][1] += a[i] * b[1];
                c[i][2] += a[i] * b[2];
                c[i][3] += a[i] * b[3];
            }
        }
        __syncthreads();
    }

    #pragma unroll
    for (int i = 0; i < 8; i++) {
        int row = row0 + ty * 8 + i;
        if (row < Mr) {
            float4 v = make_float4(c[i][0], c[i][1], c[i][2], c[i][3]);
            *reinterpret_cast<float4*>(hraw + (size_t)row * F + col0 + tx * 4) = v;
        }
    }
}

// ---------------- small-F GEMM (layer 4: K=64, F=8) -------------------------

__global__ void k_gemm_small(const float* __restrict__ X,
                             const float* __restrict__ W,
                             float* __restrict__ hraw,
                             int Mr, int K, int F) {
    __shared__ float Ws[512];
    for (int i = threadIdx.x; i < K * F; i += blockDim.x) Ws[i] = W[i];
    __syncthreads();

    int npb = blockDim.x / F;
    int n = blockIdx.x * npb + threadIdx.x / F;
    int f = threadIdx.x % F;
    if (n >= Mr) return;

    const float* xr = X + (size_t)n * K;
    float s = 0.f;
    #pragma unroll 8
    for (int k = 0; k < K; k++) s += xr[k] * Ws[k * F + f];

    hraw[(size_t)n * F + f] = s;
}

// ---------------- aggregation: warp per dst, fused finalize -----------------
// out[d] = dinv[d] * ( sum_{s in adj[d]} dinv[s]*hraw[s>>sh]
//                      + dinv[d]*hraw[d>>sh] ) + b   [, relu]

template<int F>
__global__ __launch_bounds__(256) void k_agg(
        const int*   __restrict__ adj,
        const int*   __restrict__ cnt,
        const float* __restrict__ hraw,
        const float* __restrict__ dinv,
        const float* __restrict__ bias,
        float*       __restrict__ out,
        int M, int shift, int relu) {
    int w    = (blockIdx.x * blockDim.x + threadIdx.x) >> 5;
    int lane = threadIdx.x & 31;
    if (w >= M) return;
    const int d = w;
    int n = cnt[d]; if (n > CAP) n = CAP;

    constexpr int VPT = (F >= 32) ? F / 32 : 1;
    float acc[VPT];
    #pragma unroll
    for (int v = 0; v < VPT; v++) acc[v] = 0.f;

    const int* ap = adj + (size_t)d * CAP;

    for (int i0 = 0; i0 < n; i0 += 32) {
        int rem = n - i0;
        int e  = -1;
        float scl = 0.f;
        if (lane < rem) { e = ap[i0 + lane]; scl = dinv[e]; }
        int m = rem < 32 ? rem : 32;
        for (int j = 0; j < m; j++) {
            int   s  = __shfl_sync(0xffffffffu, e,   j);
            float sc = __shfl_sync(0xffffffffu, scl, j);
            const float* hr = hraw + (size_t)(s >> shift) * F;
            if (F == 256) {
                float4 h0 = *reinterpret_cast<const float4*>(hr + lane * 4);
                float4 h1 = *reinterpret_cast<const float4*>(hr + 128 + lane * 4);
                acc[0] += sc * h0.x; acc[1] += sc * h0.y;
                acc[2] += sc * h0.z; acc[3] += sc * h0.w;
                acc[4] += sc * h1.x; acc[5] += sc * h1.y;
                acc[6] += sc * h1.z; acc[7] += sc * h1.w;
            } else if (F == 128) {
                float4 h0 = *reinterpret_cast<const float4*>(hr + lane * 4);
                acc[0] += sc * h0.x; acc[1] += sc * h0.y;
                acc[2] += sc * h0.z; acc[3] += sc * h0.w;
            } else if (F == 64) {
                float2 h0 = *reinterpret_cast<const float2*>(hr + lane * 2);
                acc[0] += sc * h0.x; acc[1] += sc * h0.y;
            } else {  // F == 8
                if (lane < 8) acc[0] += sc * hr[lane];
            }
        }
    }

    // self loop + finalize
    float dv = dinv[d];
    const float* hr = hraw + (size_t)(d >> shift) * F;
    float* op = out + (size_t)d * F;

    if (F == 256) {
        float4 h0 = *reinterpret_cast<const float4*>(hr + lane * 4);
        float4 h1 = *reinterpret_cast<const float4*>(hr + 128 + lane * 4);
        float4 b0 = *reinterpret_cast<const float4*>(bias + lane * 4);
        float4 b1 = *reinterpret_cast<const float4*>(bias + 128 + lane * 4);
        float4 o0, o1;
        o0.x = (acc[0] + dv * h0.x) * dv + b0.x;
        o0.y = (acc[1] + dv * h0.y) * dv + b0.y;
        o0.z = (acc[2] + dv * h0.z) * dv + b0.z;
        o0.w = (acc[3] + dv * h0.w) * dv + b0.w;
        o1.x = (acc[4] + dv * h1.x) * dv + b1.x;
        o1.y = (acc[5] + dv * h1.y) * dv + b1.y;
        o1.z = (acc[6] + dv * h1.z) * dv + b1.z;
        o1.w = (acc[7] + dv * h1.w) * dv + b1.w;
        if (relu) {
            o0.x = fmaxf(o0.x, 0.f); o0.y = fmaxf(o0.y, 0.f);
            o0.z = fmaxf(o0.z, 0.f); o0.w = fmaxf(o0.w, 0.f);
            o1.x = fmaxf(o1.x, 0.f); o1.y = fmaxf(o1.y, 0.f);
            o1.z = fmaxf(o1.z, 0.f); o1.w = fmaxf(o1.w, 0.f);
        }
        *reinterpret_cast<float4*>(op + lane * 4) = o0;
        *reinterpret_cast<float4*>(op + 128 + lane * 4) = o1;
    } else if (F == 128) {
        float4 h0 = *reinterpret_cast<const float4*>(hr + lane * 4);
        float4 b0 = *reinterpret_cast<const float4*>(bias + lane * 4);
        float4 o0;
        o0.x = (acc[0] + dv * h0.x) * dv + b0.x;
        o0.y = (acc[1] + dv * h0.y) * dv + b0.y;
        o0.z = (acc[2] + dv * h0.z) * dv + b0.z;
        o0.w = (acc[3] + dv * h0.w) * dv + b0.w;
        if (relu) {
            o0.x = fmaxf(o0.x, 0.f); o0.y = fmaxf(o0.y, 0.f);
            o0.z = fmaxf(o0.z, 0.f); o0.w = fmaxf(o0.w, 0.f);
        }
        *reinterpret_cast<float4*>(op + lane * 4) = o0;
    } else if (F == 64) {
        float2 h0 = *reinterpret_cast<const float2*>(hr + lane * 2);
        float2 b0 = *reinterpret_cast<const float2*>(bias + lane * 2);
        float2 o0;
        o0.x = (acc[0] + dv * h0.x) * dv + b0.x;
        o0.y = (acc[1] + dv * h0.y) * dv + b0.y;
        if (relu) { o0.x = fmaxf(o0.x, 0.f); o0.y = fmaxf(o0.y, 0.f); }
        *reinterpret_cast<float2*>(op + lane * 2) = o0;
    } else {  // F == 8
        if (lane < 8) {
            float o = (acc[0] + dv * hr[lane]) * dv + bias[lane];
            if (relu) o = fmaxf(o, 0.f);
            op[lane] = o;
        }
    }
}

// ---------------- host side -------------------------------------------------

static void gcn_layer(const float* x, const int* edges, long long E,
                      const float* W, const float* bias, float* out,
                      int M, int K, int F, int shift, int relu,
                      int* cnt, float* dinv, int* adj, float* hraw) {
    const int* src = edges;
    const int* dst = edges + E;
    const int Mr = M >> shift;                  // raw (pre-upsample) rows

    cudaMemsetAsync(cnt, 0, (size_t)M * sizeof(int));
    k_build<<<((int)E + 255) / 256, 256>>>(src, dst, cnt, adj, (int)E);
    k_rsqrt<<<(M + 255) / 256, 256>>>(cnt, dinv, M);

    if (F >= 64) {
        dim3 grid(F / 64, (Mr + 127) / 128);
        k_gemm_tiled<<<grid, 256>>>(x, W, hraw, Mr, K, F);
    } else {
        int npb = 256 / F;
        k_gemm_small<<<(Mr + npb - 1) / npb, 256>>>(x, W, hraw, Mr, K, F);
    }

    int blocks = (M + 7) / 8;                  // 8 warps per block
    if (F == 256)
        k_agg<256><<<blocks, 256>>>(adj, cnt, hraw, dinv, bias, out, M, shift, relu);
    else if (F == 128)
        k_agg<128><<<blocks, 256>>>(adj, cnt, hraw, dinv, bias, out, M, shift, relu);
    else if (F == 64)
        k_agg<64><<<blocks, 256>>>(adj, cnt, hraw, dinv, bias, out, M, shift, relu);
    else
        k_agg<8><<<blocks, 256>>>(adj, cnt, hraw, dinv, bias, out, M, shift, relu);
}

extern "C" void kernel_launch(void* const* d_in, const int* in_sizes, int n_in,
                              void* d_out, int out_size) {
    const float* z   = (const float*)d_in[0];
    const int*   e1  = (const int*)d_in[1];
    const int*   ps2 = (const int*)d_in[2];
    const int*   ps1 = (const int*)d_in[3];
    const int*   ps0 = (const int*)d_in[4];
    const float* W1 = (const float*)d_in[5];
    const float* b1 = (const float*)d_in[6];
    const float* W2 = (const float*)d_in[7];
    const float* b2 = (const float*)d_in[8];
    const float* W3 = (const float*)d_in[9];
    const float* b3 = (const float*)d_in[10];
    const float* W4 = (const float*)d_in[11];
    const float* b4 = (const float*)d_in[12];

    const int h2 = 256, h1 = 128, h0 = 64, oc = 8;
    int N = in_sizes[0] / h2;                   // 25000
    long long E1 = in_sizes[1] / 2;
    long long E2 = in_sizes[2] / 2;
    long long E3 = in_sizes[3] / 2;
    long long E4 = in_sizes[4] / 2;

    int *cnt, *adj;
    float *dinv, *hraw, *p1, *p2;
    cudaGetSymbolAddress((void**)&cnt,  g_cnt);
    cudaGetSymbolAddress((void**)&dinv, g_dinv);
    cudaGetSymbolAddress((void**)&adj,  g_adj);
    cudaGetSymbolAddress((void**)&hraw, g_hraw);
    cudaGetSymbolAddress((void**)&p1,   g_p1);
    cudaGetSymbolAddress((void**)&p2,   g_p2);

    // L1: [N, 256] -> [N, 256], relu, no upsample
    gcn_layer(z,  e1,  E1, W1, b1, p1, N,     h2, h2, 0, 1, cnt, dinv, adj, hraw);
    // L2 (upsample x2 folded): [2N] nodes, feats 256 -> 128, relu
    gcn_layer(p1, ps2, E2, W2, b2, p2, 2 * N, h2, h1, 1, 1, cnt, dinv, adj, hraw);
    // L3: [4N] nodes, 128 -> 64, relu
    gcn_layer(p2, ps1, E3, W3, b3, p1, 4 * N, h1, h0, 1, 1, cnt, dinv, adj, hraw);
    // L4: [8N] nodes, 64 -> 8, no relu, straight to d_out
    gcn_layer(p1, ps0, E4, W4, b4, (float*)d_out, 8 * N, h0, oc, 1, 0,
              cnt, dinv, adj, hraw);
}

// round 8
// speedup vs baseline: 1.6859x; 1.6859x over previous
#include <cuda_runtime.h>
#include <cstdint>

// ---------------------------------------------------------------------------
// GCN decoder: 4 x (GCNConv [+ReLU] [+upsample x2 folded into indexing])
// L1-L3 (F in {256,128,64}):  CSR-build -> GEMM -> warp-per-dst gather agg
//                             (edge loop unrolled x2/x4 for MLP)
// L4 (F=8):                   count_deg -> GEMM -> atomic scatter -> finalize
// ---------------------------------------------------------------------------

#define MAXN 200000
#define MAXF 6400000
#define CAP  64

__device__ __align__(256) int   g_cnt[MAXN];
__device__ __align__(256) float g_dinv[MAXN];
__device__ __align__(256) int   g_adj[MAXN * CAP];
__device__ __align__(256) float g_hraw[MAXF];
__device__ __align__(256) float g_acc4[1600000];   // L4 scatter accumulator
__device__ __align__(256) float g_p1  [MAXF];      // ping
__device__ __align__(256) float g_p2  [MAXF];      // pong

// ---------------- adjacency build / degree count / dinv ----------------

__global__ void k_build(const int* __restrict__ src,
                        const int* __restrict__ dst,
                        int* __restrict__ cnt,
                        int* __restrict__ adj, int E) {
    int i = blockIdx.x * blockDim.x + threadIdx.x;
    if (i < E) {
        int d = dst[i];
        int p = atomicAdd(&cnt[d], 1);
        if (p < CAP) adj[d * CAP + p] = src[i];
    }
}

__global__ void k_count_deg(const int* __restrict__ dst,
                            int* __restrict__ cnt, int E) {
    int i = blockIdx.x * blockDim.x + threadIdx.x;
    if (i < E) atomicAdd(&cnt[dst[i]], 1);
}

__global__ void k_rsqrt(const int* __restrict__ cnt,
                        float* __restrict__ dinv, int M) {
    int i = blockIdx.x * blockDim.x + threadIdx.x;
    if (i < M) dinv[i] = rsqrtf((float)cnt[i] + 1.0f);
}

// ---------------- tiled GEMM: hraw = X @ W (proven 8x4 microtile) -----------

__global__ __launch_bounds__(256) void k_gemm_tiled(
        const float* __restrict__ X,
        const float* __restrict__ W,
        float* __restrict__ hraw,
        int Mr, int K, int F) {
    __shared__ float As[16][128];
    __shared__ float Bs[16][64];

    const int tid = threadIdx.x;
    const int tx  = tid & 15;
    const int ty  = tid >> 4;
    const int row0 = blockIdx.y * 128;
    const int col0 = blockIdx.x * 64;

    const int brow = tid >> 4;
    const int bc   = (tid & 15) * 4;

    float c[8][4] = {};
    float a[8], b[4];

    for (int k0 = 0; k0 < K; k0 += 16) {
        #pragma unroll
        for (int li = 0; li < 2; li++) {
            int i = tid + li * 256;
            int r  = i >> 2;
            int kc = (i & 3) * 4;
            int grow = row0 + r;
            float4 v = make_float4(0.f, 0.f, 0.f, 0.f);
            if (grow < Mr)
                v = *reinterpret_cast<const float4*>(
                    X + (size_t)grow * K + k0 + kc);
            As[kc + 0][r] = v.x;
            As[kc + 1][r] = v.y;
            As[kc + 2][r] = v.z;
            As[kc + 3][r] = v.w;
        }
        *reinterpret_cast<float4*>(&Bs[brow][bc]) =
            *reinterpret_cast<const float4*>(W + (size_t)(k0 + brow) * F + col0 + bc);

        __syncthreads();

        #pragma unroll
        for (int kk = 0; kk < 16; kk++) {
            *reinterpret_cast<float4*>(&a[0]) = *reinterpret_cast<float4*>(&As[kk][ty * 8]);
            *reinterpret_cast<float4*>(&a[4]) = *reinterpret_cast<float4*>(&As[kk][ty * 8 + 4]);
            *reinterpret_cast<float4*>(&b[0]) = *reinterpret_cast<float4*>(&Bs[kk][tx * 4]);
            #pragma unroll
            for (int i = 0; i < 8; i++) {
                c[i][0] += a[i] * b[0];
                c[i][1] += a[i] * b[1];
                c[i][2] += a[i] * b[2];
                c[i][3] += a[i] * b[3];
            }
        }
        __syncthreads();
    }

    #pragma unroll
    for (int i = 0; i < 8; i++) {
        int row = row0 + ty * 8 + i;
        if (row < Mr) {
            float4 v = make_float4(c[i][0], c[i][1], c[i][2], c[i][3]);
            *reinterpret_cast<float4*>(hraw + (size_t)row * F + col0 + tx * 4) = v;
        }
    }
}

// ---------------- small-F GEMM (layer 4: K=64, F=8) -------------------------

__global__ void k_gemm_small(const float* __restrict__ X,
                             const float* __restrict__ W,
                             float* __restrict__ hraw,
                             int Mr, int K, int F) {
    __shared__ float Ws[512];
    for (int i = threadIdx.x; i < K * F; i += blockDim.x) Ws[i] = W[i];
    __syncthreads();

    int npb = blockDim.x / F;
    int n = blockIdx.x * npb + threadIdx.x / F;
    int f = threadIdx.x % F;
    if (n >= Mr) return;

    const float* xr = X + (size_t)n * K;
    float s = 0.f;
    #pragma unroll 8
    for (int k = 0; k < K; k++) s += xr[k] * Ws[k * F + f];

    hraw[(size_t)n * F + f] = s;
}

// ---------------- aggregation: warp per dst, MLP-unrolled edge loop ---------

template<int F>
__global__ __launch_bounds__(256) void k_agg(
        const int*   __restrict__ adj,
        const int*   __restrict__ cnt,
        const float* __restrict__ hraw,
        const float* __restrict__ dinv,
        const float* __restrict__ bias,
        float*       __restrict__ out,
        int M, int shift, int relu) {
    int w    = (blockIdx.x * blockDim.x + threadIdx.x) >> 5;
    int lane = threadIdx.x & 31;
    if (w >= M) return;
    const int d = w;
    int n = cnt[d]; if (n > CAP) n = CAP;

    constexpr int VPT = F / 32;         // 8 / 4 / 2
    float acc[VPT];
    #pragma unroll
    for (int v = 0; v < VPT; v++) acc[v] = 0.f;

    const int* ap = adj + (size_t)d * CAP;

    for (int i0 = 0; i0 < n; i0 += 32) {
        int m = n - i0; if (m > 32) m = 32;
        int e = 0; float scl = 0.f;
        if (lane < m) { e = ap[i0 + lane]; scl = dinv[e]; }

        int j = 0;
        if (F == 256) {
            for (; j + 2 <= m; j += 2) {
                int   s0 = __shfl_sync(0xffffffffu, e,   j);
                float c0 = __shfl_sync(0xffffffffu, scl, j);
                int   s1 = __shfl_sync(0xffffffffu, e,   j + 1);
                float c1 = __shfl_sync(0xffffffffu, scl, j + 1);
                const float* r0 = hraw + (size_t)(s0 >> shift) * 256;
                const float* r1 = hraw + (size_t)(s1 >> shift) * 256;
                float4 a0 = *reinterpret_cast<const float4*>(r0 + lane * 4);
                float4 b0 = *reinterpret_cast<const float4*>(r0 + 128 + lane * 4);
                float4 a1 = *reinterpret_cast<const float4*>(r1 + lane * 4);
                float4 b1 = *reinterpret_cast<const float4*>(r1 + 128 + lane * 4);
                acc[0] += c0 * a0.x; acc[1] += c0 * a0.y;
                acc[2] += c0 * a0.z; acc[3] += c0 * a0.w;
                acc[4] += c0 * b0.x; acc[5] += c0 * b0.y;
                acc[6] += c0 * b0.z; acc[7] += c0 * b0.w;
                acc[0] += c1 * a1.x; acc[1] += c1 * a1.y;
                acc[2] += c1 * a1.z; acc[3] += c1 * a1.w;
                acc[4] += c1 * b1.x; acc[5] += c1 * b1.y;
                acc[6] += c1 * b1.z; acc[7] += c1 * b1.w;
            }
        } else if (F == 128) {
            for (; j + 4 <= m; j += 4) {
                int   s0 = __shfl_sync(0xffffffffu, e,   j);
                float c0 = __shfl_sync(0xffffffffu, scl, j);
                int   s1 = __shfl_sync(0xffffffffu, e,   j + 1);
                float c1 = __shfl_sync(0xffffffffu, scl, j + 1);
                int   s2 = __shfl_sync(0xffffffffu, e,   j + 2);
                float c2 = __shfl_sync(0xffffffffu, scl, j + 2);
                int   s3 = __shfl_sync(0xffffffffu, e,   j + 3);
                float c3 = __shfl_sync(0xffffffffu, scl, j + 3);
                float4 a0 = *reinterpret_cast<const float4*>(hraw + (size_t)(s0 >> shift) * 128 + lane * 4);
                float4 a1 = *reinterpret_cast<const float4*>(hraw + (size_t)(s1 >> shift) * 128 + lane * 4);
                float4 a2 = *reinterpret_cast<const float4*>(hraw + (size_t)(s2 >> shift) * 128 + lane * 4);
                float4 a3 = *reinterpret_cast<const float4*>(hraw + (size_t)(s3 >> shift) * 128 + lane * 4);
                acc[0] += c0 * a0.x; acc[1] += c0 * a0.y; acc[2] += c0 * a0.z; acc[3] += c0 * a0.w;
                acc[0] += c1 * a1.x; acc[1] += c1 * a1.y; acc[2] += c1 * a1.z; acc[3] += c1 * a1.w;
                acc[0] += c2 * a2.x; acc[1] += c2 * a2.y; acc[2] += c2 * a2.z; acc[3] += c2 * a2.w;
                acc[0] += c3 * a3.x; acc[1] += c3 * a3.y; acc[2] += c3 * a3.z; acc[3] += c3 * a3.w;
            }
        } else {  // F == 64
            for (; j + 4 <= m; j += 4) {
                int   s0 = __shfl_sync(0xffffffffu, e,   j);
                float c0 = __shfl_sync(0xffffffffu, scl, j);
                int   s1 = __shfl_sync(0xffffffffu, e,   j + 1);
                float c1 = __shfl_sync(0xffffffffu, scl, j + 1);
                int   s2 = __shfl_sync(0xffffffffu, e,   j + 2);
                float c2 = __shfl_sync(0xffffffffu, scl, j + 2);
                int   s3 = __shfl_sync(0xffffffffu, e,   j + 3);
                float c3 = __shfl_sync(0xffffffffu, scl, j + 3);
                float2 a0 = *reinterpret_cast<const float2*>(hraw + (size_t)(s0 >> shift) * 64 + lane * 2);
                float2 a1 = *reinterpret_cast<const float2*>(hraw + (size_t)(s1 >> shift) * 64 + lane * 2);
                float2 a2 = *reinterpret_cast<const float2*>(hraw + (size_t)(s2 >> shift) * 64 + lane * 2);
                float2 a3 = *reinterpret_cast<const float2*>(hraw + (size_t)(s3 >> shift) * 64 + lane * 2);
                acc[0] += c0 * a0.x; acc[1] += c0 * a0.y;
                acc[0] += c1 * a1.x; acc[1] += c1 * a1.y;
                acc[0] += c2 * a2.x; acc[1] += c2 * a2.y;
                acc[0] += c3 * a3.x; acc[1] += c3 * a3.y;
            }
        }
        // tail
        for (; j < m; j++) {
            int   s  = __shfl_sync(0xffffffffu, e,   j);
            float sc = __shfl_sync(0xffffffffu, scl, j);
            const float* hr = hraw + (size_t)(s >> shift) * F;
            if (F == 256) {
                float4 a0 = *reinterpret_cast<const float4*>(hr + lane * 4);
                float4 b0 = *reinterpret_cast<const float4*>(hr + 128 + lane * 4);
                acc[0] += sc * a0.x; acc[1] += sc * a0.y;
                acc[2] += sc * a0.z; acc[3] += sc * a0.w;
                acc[VPT > 4 ? 4 : 0] += sc * b0.x;
                acc[VPT > 5 ? 5 : 0] += sc * b0.y;
                acc[VPT > 6 ? 6 : 0] += sc * b0.z;
                acc[VPT > 7 ? 7 : 0] += sc * b0.w;
            } else if (F == 128) {
                float4 a0 = *reinterpret_cast<const float4*>(hr + lane * 4);
                acc[0] += sc * a0.x; acc[1] += sc * a0.y;
                acc[VPT > 2 ? 2 : 0] += sc * a0.z;
                acc[VPT > 3 ? 3 : 0] += sc * a0.w;
            } else {
                float2 a0 = *reinterpret_cast<const float2*>(hr + lane * 2);
                acc[0] += sc * a0.x;
                acc[VPT > 1 ? 1 : 0] += sc * a0.y;
            }
        }
    }

    // self loop + finalize
    float dv = dinv[d];
    const float* hr = hraw + (size_t)(d >> shift) * F;
    float* op = out + (size_t)d * F;

    if (F == 256) {
        float4 h0 = *reinterpret_cast<const float4*>(hr + lane * 4);
        float4 h1 = *reinterpret_cast<const float4*>(hr + 128 + lane * 4);
        float4 b0 = *reinterpret_cast<const float4*>(bias + lane * 4);
        float4 b1 = *reinterpret_cast<const float4*>(bias + 128 + lane * 4);
        float4 o0, o1;
        o0.x = (acc[0] + dv * h0.x) * dv + b0.x;
        o0.y = (acc[1] + dv * h0.y) * dv + b0.y;
        o0.z = (acc[2] + dv * h0.z) * dv + b0.z;
        o0.w = (acc[3] + dv * h0.w) * dv + b0.w;
        o1.x = (acc[VPT > 4 ? 4 : 0] + dv * h1.x) * dv + b1.x;
        o1.y = (acc[VPT > 5 ? 5 : 0] + dv * h1.y) * dv + b1.y;
        o1.z = (acc[VPT > 6 ? 6 : 0] + dv * h1.z) * dv + b1.z;
        o1.w = (acc[VPT > 7 ? 7 : 0] + dv * h1.w) * dv + b1.w;
        if (relu) {
            o0.x = fmaxf(o0.x, 0.f); o0.y = fmaxf(o0.y, 0.f);
            o0.z = fmaxf(o0.z, 0.f); o0.w = fmaxf(o0.w, 0.f);
            o1.x = fmaxf(o1.x, 0.f); o1.y = fmaxf(o1.y, 0.f);
            o1.z = fmaxf(o1.z, 0.f); o1.w = fmaxf(o1.w, 0.f);
        }
        *reinterpret_cast<float4*>(op + lane * 4) = o0;
        *reinterpret_cast<float4*>(op + 128 + lane * 4) = o1;
    } else if (F == 128) {
        float4 h0 = *reinterpret_cast<const float4*>(hr + lane * 4);
        float4 b0 = *reinterpret_cast<const float4*>(bias + lane * 4);
        float4 o0;
        o0.x = (acc[0] + dv * h0.x) * dv + b0.x;
        o0.y = (acc[1] + dv * h0.y) * dv + b0.y;
        o0.z = (acc[VPT > 2 ? 2 : 0] + dv * h0.z) * dv + b0.z;
        o0.w = (acc[VPT > 3 ? 3 : 0] + dv * h0.w) * dv + b0.w;
        if (relu) {
            o0.x = fmaxf(o0.x, 0.f); o0.y = fmaxf(o0.y, 0.f);
            o0.z = fmaxf(o0.z, 0.f); o0.w = fmaxf(o0.w, 0.f);
        }
        *reinterpret_cast<float4*>(op + lane * 4) = o0;
    } else {  // F == 64
        float2 h0 = *reinterpret_cast<const float2*>(hr + lane * 2);
        float2 b0 = *reinterpret_cast<const float2*>(bias + lane * 2);
        float2 o0;
        o0.x = (acc[0] + dv * h0.x) * dv + b0.x;
        o0.y = (acc[VPT > 1 ? 1 : 0] + dv * h0.y) * dv + b0.y;
        if (relu) { o0.x = fmaxf(o0.x, 0.f); o0.y = fmaxf(o0.y, 0.f); }
        *reinterpret_cast<float2*>(op + lane * 2) = o0;
    }
}

// ---------------- L4 scatter + finalize (proven R6 path) --------------------

__device__ __forceinline__ void red_add_v4(float4* addr, float4 v) {
    asm volatile("red.global.add.v4.f32 [%0], {%1, %2, %3, %4};"
                 :: "l"(addr), "f"(v.x), "f"(v.y), "f"(v.z), "f"(v.w)
                 : "memory");
}

__global__ void k_scatter8(const int* __restrict__ src,
                           const int* __restrict__ dst,
                           const float* __restrict__ hraw,
                           const float* __restrict__ dinv,
                           float* __restrict__ acc,
                           int total) {             // F=8, lf4=1, shift=1
    int idx = blockIdx.x * blockDim.x + threadIdx.x;
    if (idx >= total) return;
    int e = idx >> 1;
    int c = idx & 1;
    int s = src[e];
    int d = dst[e];
    float sc = dinv[s];
    const float4* h4 = reinterpret_cast<const float4*>(hraw);
    float4 v = h4[((s >> 1) << 1) + c];
    v.x *= sc; v.y *= sc; v.z *= sc; v.w *= sc;
    red_add_v4(reinterpret_cast<float4*>(acc) + ((d << 1) + c), v);
}

__global__ void k_finalize8(const float* __restrict__ acc,
                            const float* __restrict__ hraw,
                            const float* __restrict__ dinv,
                            const float* __restrict__ bias,
                            float* __restrict__ out,
                            int total4) {           // F=8, lf4=1, shift=1
    int idx = blockIdx.x * blockDim.x + threadIdx.x;
    if (idx >= total4) return;
    int n = idx >> 1;
    int c = idx & 1;
    float dv = dinv[n];
    float4 a = reinterpret_cast<const float4*>(acc)[idx];
    float4 h = reinterpret_cast<const float4*>(hraw)[((n >> 1) << 1) + c];
    float4 b = reinterpret_cast<const float4*>(bias)[c];
    a.x = (a.x + dv * h.x) * dv + b.x;
    a.y = (a.y + dv * h.y) * dv + b.y;
    a.z = (a.z + dv * h.z) * dv + b.z;
    a.w = (a.w + dv * h.w) * dv + b.w;
    reinterpret_cast<float4*>(out)[idx] = a;
}

// ---------------- host side -------------------------------------------------

static void gcn_layer_agg(const float* x, const int* edges, long long E,
                          const float* W, const float* bias, float* out,
                          int M, int K, int F, int shift, int relu,
                          int* cnt, float* dinv, int* adj, float* hraw) {
    const int* src = edges;
    const int* dst = edges + E;
    const int Mr = M >> shift;

    cudaMemsetAsync(cnt, 0, (size_t)M * sizeof(int));
    k_build<<<((int)E + 255) / 256, 256>>>(src, dst, cnt, adj, (int)E);
    k_rsqrt<<<(M + 255) / 256, 256>>>(cnt, dinv, M);

    dim3 grid(F / 64, (Mr + 127) / 128);
    k_gemm_tiled<<<grid, 256>>>(x, W, hraw, Mr, K, F);

    int blocks = (M + 7) / 8;
    if (F == 256)
        k_agg<256><<<blocks, 256>>>(adj, cnt, hraw, dinv, bias, out, M, shift, relu);
    else if (F == 128)
        k_agg<128><<<blocks, 256>>>(adj, cnt, hraw, dinv, bias, out, M, shift, relu);
    else
        k_agg<64><<<blocks, 256>>>(adj, cnt, hraw, dinv, bias, out, M, shift, relu);
}

static void gcn_layer4(const float* x, const int* edges, long long E,
                       const float* W, const float* bias, float* out,
                       int M, int K,
                       int* cnt, float* dinv, float* hraw, float* acc) {
    const int* src = edges;
    const int* dst = edges + E;
    const int Mr = M >> 1;
    const int F = 8;

    cudaMemsetAsync(cnt, 0, (size_t)M * sizeof(int));
    cudaMemsetAsync(acc, 0, (size_t)M * F * sizeof(float));
    k_count_deg<<<((int)E + 255) / 256, 256>>>(dst, cnt, (int)E);
    k_rsqrt<<<(M + 255) / 256, 256>>>(cnt, dinv, M);

    int npb = 256 / F;
    k_gemm_small<<<(Mr + npb - 1) / npb, 256>>>(x, W, hraw, Mr, K, F);

    int totE = (int)E * 2;                       // E * F/4
    k_scatter8<<<(totE + 255) / 256, 256>>>(src, dst, hraw, dinv, acc, totE);

    int tot4 = M * 2;
    k_finalize8<<<(tot4 + 255) / 256, 256>>>(acc, hraw, dinv, bias, out, tot4);
}

extern "C" void kernel_launch(void* const* d_in, const int* in_sizes, int n_in,
                              void* d_out, int out_size) {
    const float* z   = (const float*)d_in[0];
    const int*   e1  = (const int*)d_in[1];
    const int*   ps2 = (const int*)d_in[2];
    const int*   ps1 = (const int*)d_in[3];
    const int*   ps0 = (const int*)d_in[4];
    const float* W1 = (const float*)d_in[5];
    const float* b1 = (const float*)d_in[6];
    const float* W2 = (const float*)d_in[7];
    const float* b2 = (const float*)d_in[8];
    const float* W3 = (const float*)d_in[9];
    const float* b3 = (const float*)d_in[10];
    const float* W4 = (const float*)d_in[11];
    const float* b4 = (const float*)d_in[12];

    const int h2 = 256, h1 = 128, h0 = 64;
    int N = in_sizes[0] / h2;                   // 25000
    long long E1 = in_sizes[1] / 2;
    long long E2 = in_sizes[2] / 2;
    long long E3 = in_sizes[3] / 2;
    long long E4 = in_sizes[4] / 2;

    int *cnt, *adj;
    float *dinv, *hraw, *acc4, *p1, *p2;
    cudaGetSymbolAddress((void**)&cnt,  g_cnt);
    cudaGetSymbolAddress((void**)&dinv, g_dinv);
    cudaGetSymbolAddress((void**)&adj,  g_adj);
    cudaGetSymbolAddress((void**)&hraw, g_hraw);
    cudaGetSymbolAddress((void**)&acc4, g_acc4);
    cudaGetSymbolAddress((void**)&p1,   g_p1);
    cudaGetSymbolAddress((void**)&p2,   g_p2);

    // L1: [N, 256] -> [N, 256], relu, no upsample
    gcn_layer_agg(z,  e1,  E1, W1, b1, p1, N,     h2, h2, 0, 1, cnt, dinv, adj, hraw);
    // L2 (upsample x2 folded): [2N] nodes, 256 -> 128, relu
    gcn_layer_agg(p1, ps2, E2, W2, b2, p2, 2 * N, h2, h1, 1, 1, cnt, dinv, adj, hraw);
    // L3: [4N] nodes, 128 -> 64, relu
    gcn_layer_agg(p2, ps1, E3, W3, b3, p1, 4 * N, h1, h0, 1, 1, cnt, dinv, adj, hraw);
    // L4: [8N] nodes, 64 -> 8, no relu, straight to d_out
    gcn_layer4(p1, ps0, E4, W4, b4, (float*)d_out, 8 * N, h0,
               cnt, dinv, hraw, acc4);
}

// round 9
// speedup vs baseline: 1.7361x; 1.0298x over previous
#include <cuda_runtime.h>
#include <cstdint>

// ---------------------------------------------------------------------------
// GCN decoder: 4 x (GCNConv [+ReLU] [+upsample x2 folded into indexing])
// L1-L3 (F in {256,128,64}):  CSR-build -> GEMM(f32x2) -> warp-per-dst agg
// L4 (F=8):                   count_deg -> GEMM -> atomic scatter -> finalize
// GEMM inner loop uses packed fma.rn.f32x2 (2 fp32 MACs / instruction).
// ---------------------------------------------------------------------------

#define MAXN 200000
#define MAXF 6400000
#define CAP  64

__device__ __align__(256) int   g_cnt[MAXN];
__device__ __align__(256) float g_dinv[MAXN];
__device__ __align__(256) int   g_adj[MAXN * CAP];
__device__ __align__(256) float g_hraw[MAXF];
__device__ __align__(256) float g_acc4[1600000];   // L4 scatter accumulator
__device__ __align__(256) float g_p1  [MAXF];      // ping
__device__ __align__(256) float g_p2  [MAXF];      // pong

// ---------------- adjacency build / degree count / dinv ----------------

__global__ void k_build(const int* __restrict__ src,
                        const int* __restrict__ dst,
                        int* __restrict__ cnt,
                        int* __restrict__ adj, int E) {
    int i = blockIdx.x * blockDim.x + threadIdx.x;
    if (i < E) {
        int d = dst[i];
        int p = atomicAdd(&cnt[d], 1);
        if (p < CAP) adj[d * CAP + p] = src[i];
    }
}

__global__ void k_count_deg(const int* __restrict__ dst,
                            int* __restrict__ cnt, int E) {
    int i = blockIdx.x * blockDim.x + threadIdx.x;
    if (i < E) atomicAdd(&cnt[dst[i]], 1);
}

__global__ void k_rsqrt(const int* __restrict__ cnt,
                        float* __restrict__ dinv, int M) {
    int i = blockIdx.x * blockDim.x + threadIdx.x;
    if (i < M) dinv[i] = rsqrtf((float)cnt[i] + 1.0f);
}

// ---------------- f32x2 helpers ----------------

__device__ __forceinline__ uint64_t bcast_f32x2(float x) {
    uint64_t r;
    uint32_t b = __float_as_uint(x);
    asm("mov.b64 %0, {%1, %1};" : "=l"(r) : "r"(b));
    return r;
}

__device__ __forceinline__ void fma_f32x2(uint64_t& c, uint64_t a, uint64_t b) {
    asm("fma.rn.f32x2 %0, %1, %2, %0;" : "+l"(c) : "l"(a), "l"(b));
}

__device__ __forceinline__ float2 unpack_f32x2(uint64_t p) {
    uint32_t lo, hi;
    asm("mov.b64 {%0, %1}, %2;" : "=r"(lo), "=r"(hi) : "l"(p));
    return make_float2(__uint_as_float(lo), __uint_as_float(hi));
}

// ---------------- tiled GEMM: hraw = X @ W ----------------------------------
// BM=128, BN=64, BK=16, 256 threads, 8x4 microtile via packed f32x2:
// accumulators = 4 row-pairs x 4 cols, 16 FFMA2 per kk (64 MACs).

__global__ __launch_bounds__(256) void k_gemm_tiled(
        const float* __restrict__ X,
        const float* __restrict__ W,
        float* __restrict__ hraw,
        int Mr, int K, int F) {
    __shared__ float As[16][128];   // transposed: As[k][row]
    __shared__ float Bs[16][64];

    const int tid = threadIdx.x;
    const int tx  = tid & 15;        // 0..15 -> 4 cols each
    const int ty  = tid >> 4;        // 0..15 -> 8 rows each
    const int row0 = blockIdx.y * 128;
    const int col0 = blockIdx.x * 64;

    const int brow = tid >> 4;
    const int bc   = (tid & 15) * 4;

    uint64_t cc[4][4] = {};          // [row-pair][col], packed f32x2

    for (int k0 = 0; k0 < K; k0 += 16) {
        #pragma unroll
        for (int li = 0; li < 2; li++) {
            int i = tid + li * 256;
            int r  = i >> 2;
            int kc = (i & 3) * 4;
            int grow = row0 + r;
            float4 v = make_float4(0.f, 0.f, 0.f, 0.f);
            if (grow < Mr)
                v = *reinterpret_cast<const float4*>(
                    X + (size_t)grow * K + k0 + kc);
            As[kc + 0][r] = v.x;
            As[kc + 1][r] = v.y;
            As[kc + 2][r] = v.z;
            As[kc + 3][r] = v.w;
        }
        *reinterpret_cast<float4*>(&Bs[brow][bc]) =
            *reinterpret_cast<const float4*>(W + (size_t)(k0 + brow) * F + col0 + bc);

        __syncthreads();

        #pragma unroll
        for (int kk = 0; kk < 16; kk++) {
            // 8 consecutive A rows = 4 packed pairs (free reinterpret, 32B aligned)
            const uint64_t* ap = reinterpret_cast<const uint64_t*>(&As[kk][ty * 8]);
            uint64_t a0 = ap[0], a1 = ap[1], a2 = ap[2], a3 = ap[3];
            float4 b = *reinterpret_cast<const float4*>(&Bs[kk][tx * 4]);
            uint64_t b0 = bcast_f32x2(b.x);
            uint64_t b1 = bcast_f32x2(b.y);
            uint64_t b2 = bcast_f32x2(b.z);
            uint64_t b3 = bcast_f32x2(b.w);
            fma_f32x2(cc[0][0], a0, b0); fma_f32x2(cc[0][1], a0, b1);
            fma_f32x2(cc[0][2], a0, b2); fma_f32x2(cc[0][3], a0, b3);
            fma_f32x2(cc[1][0], a1, b0); fma_f32x2(cc[1][1], a1, b1);
            fma_f32x2(cc[1][2], a1, b2); fma_f32x2(cc[1][3], a1, b3);
            fma_f32x2(cc[2][0], a2, b0); fma_f32x2(cc[2][1], a2, b1);
            fma_f32x2(cc[2][2], a2, b2); fma_f32x2(cc[2][3], a2, b3);
            fma_f32x2(cc[3][0], a3, b0); fma_f32x2(cc[3][1], a3, b1);
            fma_f32x2(cc[3][2], a3, b2); fma_f32x2(cc[3][3], a3, b3);
        }
        __syncthreads();
    }

    #pragma unroll
    for (int p = 0; p < 4; p++) {
        float2 v0 = unpack_f32x2(cc[p][0]);
        float2 v1 = unpack_f32x2(cc[p][1]);
        float2 v2 = unpack_f32x2(cc[p][2]);
        float2 v3 = unpack_f32x2(cc[p][3]);
        int rowA = row0 + ty * 8 + 2 * p;
        int rowB = rowA + 1;
        if (rowA < Mr) {
            float4 o = make_float4(v0.x, v1.x, v2.x, v3.x);
            *reinterpret_cast<float4*>(hraw + (size_t)rowA * F + col0 + tx * 4) = o;
        }
        if (rowB < Mr) {
            float4 o = make_float4(v0.y, v1.y, v2.y, v3.y);
            *reinterpret_cast<float4*>(hraw + (size_t)rowB * F + col0 + tx * 4) = o;
        }
    }
}

// ---------------- small-F GEMM (layer 4: K=64, F=8) -------------------------

__global__ void k_gemm_small(const float* __restrict__ X,
                             const float* __restrict__ W,
                             float* __restrict__ hraw,
                             int Mr, int K, int F) {
    __shared__ float Ws[512];
    for (int i = threadIdx.x; i < K * F; i += blockDim.x) Ws[i] = W[i];
    __syncthreads();

    int npb = blockDim.x / F;
    int n = blockIdx.x * npb + threadIdx.x / F;
    int f = threadIdx.x % F;
    if (n >= Mr) return;

    const float* xr = X + (size_t)n * K;
    float s = 0.f;
    #pragma unroll 8
    for (int k = 0; k < K; k++) s += xr[k] * Ws[k * F + f];

    hraw[(size_t)n * F + f] = s;
}

// ---------------- aggregation: warp per dst, MLP-unrolled edge loop ---------

template<int F>
__global__ __launch_bounds__(256) void k_agg(
        const int*   __restrict__ adj,
        const int*   __restrict__ cnt,
        const float* __restrict__ hraw,
        const float* __restrict__ dinv,
        const float* __restrict__ bias,
        float*       __restrict__ out,
        int M, int shift, int relu) {
    int w    = (blockIdx.x * blockDim.x + threadIdx.x) >> 5;
    int lane = threadIdx.x & 31;
    if (w >= M) return;
    const int d = w;
    int n = cnt[d]; if (n > CAP) n = CAP;

    constexpr int VPT = F / 32;         // 8 / 4 / 2
    float acc[VPT];
    #pragma unroll
    for (int v = 0; v < VPT; v++) acc[v] = 0.f;

    const int* ap = adj + (size_t)d * CAP;

    for (int i0 = 0; i0 < n; i0 += 32) {
        int m = n - i0; if (m > 32) m = 32;
        int e = 0; float scl = 0.f;
        if (lane < m) { e = ap[i0 + lane]; scl = dinv[e]; }

        int j = 0;
        if (F == 256) {
            for (; j + 2 <= m; j += 2) {
                int   s0 = __shfl_sync(0xffffffffu, e,   j);
                float c0 = __shfl_sync(0xffffffffu, scl, j);
                int   s1 = __shfl_sync(0xffffffffu, e,   j + 1);
                float c1 = __shfl_sync(0xffffffffu, scl, j + 1);
                const float* r0 = hraw + (size_t)(s0 >> shift) * 256;
                const float* r1 = hraw + (size_t)(s1 >> shift) * 256;
                float4 a0 = *reinterpret_cast<const float4*>(r0 + lane * 4);
                float4 b0 = *reinterpret_cast<const float4*>(r0 + 128 + lane * 4);
                float4 a1 = *reinterpret_cast<const float4*>(r1 + lane * 4);
                float4 b1 = *reinterpret_cast<const float4*>(r1 + 128 + lane * 4);
                acc[0] += c0 * a0.x; acc[1] += c0 * a0.y;
                acc[2] += c0 * a0.z; acc[3] += c0 * a0.w;
                acc[4] += c0 * b0.x; acc[5] += c0 * b0.y;
                acc[6] += c0 * b0.z; acc[7] += c0 * b0.w;
                acc[0] += c1 * a1.x; acc[1] += c1 * a1.y;
                acc[2] += c1 * a1.z; acc[3] += c1 * a1.w;
                acc[4] += c1 * b1.x; acc[5] += c1 * b1.y;
                acc[6] += c1 * b1.z; acc[7] += c1 * b1.w;
            }
        } else if (F == 128) {
            for (; j + 4 <= m; j += 4) {
                int   s0 = __shfl_sync(0xffffffffu, e,   j);
                float c0 = __shfl_sync(0xffffffffu, scl, j);
                int   s1 = __shfl_sync(0xffffffffu, e,   j + 1);
                float c1 = __shfl_sync(0xffffffffu, scl, j + 1);
                int   s2 = __shfl_sync(0xffffffffu, e,   j + 2);
                float c2 = __shfl_sync(0xffffffffu, scl, j + 2);
                int   s3 = __shfl_sync(0xffffffffu, e,   j + 3);
                float c3 = __shfl_sync(0xffffffffu, scl, j + 3);
                float4 a0 = *reinterpret_cast<const float4*>(hraw + (size_t)(s0 >> shift) * 128 + lane * 4);
                float4 a1 = *reinterpret_cast<const float4*>(hraw + (size_t)(s1 >> shift) * 128 + lane * 4);
                float4 a2 = *reinterpret_cast<const float4*>(hraw + (size_t)(s2 >> shift) * 128 + lane * 4);
                float4 a3 = *reinterpret_cast<const float4*>(hraw + (size_t)(s3 >> shift) * 128 + lane * 4);
                acc[0] += c0 * a0.x; acc[1] += c0 * a0.y; acc[2] += c0 * a0.z; acc[3] += c0 * a0.w;
                acc[0] += c1 * a1.x; acc[1] += c1 * a1.y; acc[2] += c1 * a1.z; acc[3] += c1 * a1.w;
                acc[0] += c2 * a2.x; acc[1] += c2 * a2.y; acc[2] += c2 * a2.z; acc[3] += c2 * a2.w;
                acc[0] += c3 * a3.x; acc[1] += c3 * a3.y; acc[2] += c3 * a3.z; acc[3] += c3 * a3.w;
            }
        } else {  // F == 64
            for (; j + 4 <= m; j += 4) {
                int   s0 = __shfl_sync(0xffffffffu, e,   j);
                float c0 = __shfl_sync(0xffffffffu, scl, j);
                int   s1 = __shfl_sync(0xffffffffu, e,   j + 1);
                float c1 = __shfl_sync(0xffffffffu, scl, j + 1);
                int   s2 = __shfl_sync(0xffffffffu, e,   j + 2);
                float c2 = __shfl_sync(0xffffffffu, scl, j + 2);
                int   s3 = __shfl_sync(0xffffffffu, e,   j + 3);
                float c3 = __shfl_sync(0xffffffffu, scl, j + 3);
                float2 a0 = *reinterpret_cast<const float2*>(hraw + (size_t)(s0 >> shift) * 64 + lane * 2);
                float2 a1 = *reinterpret_cast<const float2*>(hraw + (size_t)(s1 >> shift) * 64 + lane * 2);
                float2 a2 = *reinterpret_cast<const float2*>(hraw + (size_t)(s2 >> shift) * 64 + lane * 2);
                float2 a3 = *reinterpret_cast<const float2*>(hraw + (size_t)(s3 >> shift) * 64 + lane * 2);
                acc[0] += c0 * a0.x; acc[1] += c0 * a0.y;
                acc[0] += c1 * a1.x; acc[1] += c1 * a1.y;
                acc[0] += c2 * a2.x; acc[1] += c2 * a2.y;
                acc[0] += c3 * a3.x; acc[1] += c3 * a3.y;
            }
        }
        // tail
        for (; j < m; j++) {
            int   s  = __shfl_sync(0xffffffffu, e,   j);
            float sc = __shfl_sync(0xffffffffu, scl, j);
            const float* hr = hraw + (size_t)(s >> shift) * F;
            if (F == 256) {
                float4 a0 = *reinterpret_cast<const float4*>(hr + lane * 4);
                float4 b0 = *reinterpret_cast<const float4*>(hr + 128 + lane * 4);
                acc[0] += sc * a0.x; acc[1] += sc * a0.y;
                acc[2] += sc * a0.z; acc[3] += sc * a0.w;
                acc[VPT > 4 ? 4 : 0] += sc * b0.x;
                acc[VPT > 5 ? 5 : 0] += sc * b0.y;
                acc[VPT > 6 ? 6 : 0] += sc * b0.z;
                acc[VPT > 7 ? 7 : 0] += sc * b0.w;
            } else if (F == 128) {
                float4 a0 = *reinterpret_cast<const float4*>(hr + lane * 4);
                acc[0] += sc * a0.x; acc[1] += sc * a0.y;
                acc[VPT > 2 ? 2 : 0] += sc * a0.z;
                acc[VPT > 3 ? 3 : 0] += sc * a0.w;
            } else {
                float2 a0 = *reinterpret_cast<const float2*>(hr + lane * 2);
                acc[0] += sc * a0.x;
                acc[VPT > 1 ? 1 : 0] += sc * a0.y;
            }
        }
    }

    // self loop + finalize
    float dv = dinv[d];
    const float* hr = hraw + (size_t)(d >> shift) * F;
    float* op = out + (size_t)d * F;

    if (F == 256) {
        float4 h0 = *reinterpret_cast<const float4*>(hr + lane * 4);
        float4 h1 = *reinterpret_cast<const float4*>(hr + 128 + lane * 4);
        float4 b0 = *reinterpret_cast<const float4*>(bias + lane * 4);
        float4 b1 = *reinterpret_cast<const float4*>(bias + 128 + lane * 4);
        float4 o0, o1;
        o0.x = (acc[0] + dv * h0.x) * dv + b0.x;
        o0.y = (acc[1] + dv * h0.y) * dv + b0.y;
        o0.z = (acc[2] + dv * h0.z) * dv + b0.z;
        o0.w = (acc[3] + dv * h0.w) * dv + b0.w;
        o1.x = (acc[VPT > 4 ? 4 : 0] + dv * h1.x) * dv + b1.x;
        o1.y = (acc[VPT > 5 ? 5 : 0] + dv * h1.y) * dv + b1.y;
        o1.z = (acc[VPT > 6 ? 6 : 0] + dv * h1.z) * dv + b1.z;
        o1.w = (acc[VPT > 7 ? 7 : 0] + dv * h1.w) * dv + b1.w;
        if (relu) {
            o0.x = fmaxf(o0.x, 0.f); o0.y = fmaxf(o0.y, 0.f);
            o0.z = fmaxf(o0.z, 0.f); o0.w = fmaxf(o0.w, 0.f);
            o1.x = fmaxf(o1.x, 0.f); o1.y = fmaxf(o1.y, 0.f);
            o1.z = fmaxf(o1.z, 0.f); o1.w = fmaxf(o1.w, 0.f);
        }
        *reinterpret_cast<float4*>(op + lane * 4) = o0;
        *reinterpret_cast<float4*>(op + 128 + lane * 4) = o1;
    } else if (F == 128) {
        float4 h0 = *reinterpret_cast<const float4*>(hr + lane * 4);
        float4 b0 = *reinterpret_cast<const float4*>(bias + lane * 4);
        float4 o0;
        o0.x = (acc[0] + dv * h0.x) * dv + b0.x;
        o0.y = (acc[1] + dv * h0.y) * dv + b0.y;
        o0.z = (acc[VPT > 2 ? 2 : 0] + dv * h0.z) * dv + b0.z;
        o0.w = (acc[VPT > 3 ? 3 : 0] + dv * h0.w) * dv + b0.w;
        if (relu) {
            o0.x = fmaxf(o0.x, 0.f); o0.y = fmaxf(o0.y, 0.f);
            o0.z = fmaxf(o0.z, 0.f); o0.w = fmaxf(o0.w, 0.f);
        }
        *reinterpret_cast<float4*>(op + lane * 4) = o0;
    } else {  // F == 64
        float2 h0 = *reinterpret_cast<const float2*>(hr + lane * 2);
        float2 b0 = *reinterpret_cast<const float2*>(bias + lane * 2);
        float2 o0;
        o0.x = (acc[0] + dv * h0.x) * dv + b0.x;
        o0.y = (acc[VPT > 1 ? 1 : 0] + dv * h0.y) * dv + b0.y;
        if (relu) { o0.x = fmaxf(o0.x, 0.f); o0.y = fmaxf(o0.y, 0.f); }
        *reinterpret_cast<float2*>(op + lane * 2) = o0;
    }
}

// ---------------- L4 scatter + finalize --------------------------------------

__device__ __forceinline__ void red_add_v4(float4* addr, float4 v) {
    asm volatile("red.global.add.v4.f32 [%0], {%1, %2, %3, %4};"
                 :: "l"(addr), "f"(v.x), "f"(v.y), "f"(v.z), "f"(v.w)
                 : "memory");
}

__global__ void k_scatter8(const int* __restrict__ src,
                           const int* __restrict__ dst,
                           const float* __restrict__ hraw,
                           const float* __restrict__ dinv,
                           float* __restrict__ acc,
                           int total) {             // F=8, lf4=1, shift=1
    int idx = blockIdx.x * blockDim.x + threadIdx.x;
    if (idx >= total) return;
    int e = idx >> 1;
    int c = idx & 1;
    int s = src[e];
    int d = dst[e];
    float sc = dinv[s];
    const float4* h4 = reinterpret_cast<const float4*>(hraw);
    float4 v = h4[((s >> 1) << 1) + c];
    v.x *= sc; v.y *= sc; v.z *= sc; v.w *= sc;
    red_add_v4(reinterpret_cast<float4*>(acc) + ((d << 1) + c), v);
}

__global__ void k_finalize8(const float* __restrict__ acc,
                            const float* __restrict__ hraw,
                            const float* __restrict__ dinv,
                            const float* __restrict__ bias,
                            float* __restrict__ out,
                            int total4) {           // F=8, lf4=1, shift=1
    int idx = blockIdx.x * blockDim.x + threadIdx.x;
    if (idx >= total4) return;
    int n = idx >> 1;
    int c = idx & 1;
    float dv = dinv[n];
    float4 a = reinterpret_cast<const float4*>(acc)[idx];
    float4 h = reinterpret_cast<const float4*>(hraw)[((n >> 1) << 1) + c];
    float4 b = reinterpret_cast<const float4*>(bias)[c];
    a.x = (a.x + dv * h.x) * dv + b.x;
    a.y = (a.y + dv * h.y) * dv + b.y;
    a.z = (a.z + dv * h.z) * dv + b.z;
    a.w = (a.w + dv * h.w) * dv + b.w;
    reinterpret_cast<float4*>(out)[idx] = a;
}

// ---------------- host side -------------------------------------------------

static void gcn_layer_agg(const float* x, const int* edges, long long E,
                          const float* W, const float* bias, float* out,
                          int M, int K, int F, int shift, int relu,
                          int* cnt, float* dinv, int* adj, float* hraw) {
    const int* src = edges;
    const int* dst = edges + E;
    const int Mr = M >> shift;

    cudaMemsetAsync(cnt, 0, (size_t)M * sizeof(int));
    k_build<<<((int)E + 255) / 256, 256>>>(src, dst, cnt, adj, (int)E);
    k_rsqrt<<<(M + 255) / 256, 256>>>(cnt, dinv, M);

    dim3 grid(F / 64, (Mr + 127) / 128);
    k_gemm_tiled<<<grid, 256>>>(x, W, hraw, Mr, K, F);

    int blocks = (M + 7) / 8;
    if (F == 256)
        k_agg<256><<<blocks, 256>>>(adj, cnt, hraw, dinv, bias, out, M, shift, relu);
    else if (F == 128)
        k_agg<128><<<blocks, 256>>>(adj, cnt, hraw, dinv, bias, out, M, shift, relu);
    else
        k_agg<64><<<blocks, 256>>>(adj, cnt, hraw, dinv, bias, out, M, shift, relu);
}

static void gcn_layer4(const float* x, const int* edges, long long E,
                       const float* W, const float* bias, float* out,
                       int M, int K,
                       int* cnt, float* dinv, float* hraw, float* acc) {
    const int* src = edges;
    const int* dst = edges + E;
    const int Mr = M >> 1;
    const int F = 8;

    cudaMemsetAsync(cnt, 0, (size_t)M * sizeof(int));
    cudaMemsetAsync(acc, 0, (size_t)M * F * sizeof(float));
    k_count_deg<<<((int)E + 255) / 256, 256>>>(dst, cnt, (int)E);
    k_rsqrt<<<(M + 255) / 256, 256>>>(cnt, dinv, M);

    int npb = 256 / F;
    k_gemm_small<<<(Mr + npb - 1) / npb, 256>>>(x, W, hraw, Mr, K, F);

    int totE = (int)E * 2;                       // E * F/4
    k_scatter8<<<(totE + 255) / 256, 256>>>(src, dst, hraw, dinv, acc, totE);

    int tot4 = M * 2;
    k_finalize8<<<(tot4 + 255) / 256, 256>>>(acc, hraw, dinv, bias, out, tot4);
}

extern "C" void kernel_launch(void* const* d_in, const int* in_sizes, int n_in,
                              void* d_out, int out_size) {
    const float* z   = (const float*)d_in[0];
    const int*   e1  = (const int*)d_in[1];
    const int*   ps2 = (const int*)d_in[2];
    const int*   ps1 = (const int*)d_in[3];
    const int*   ps0 = (const int*)d_in[4];
    const float* W1 = (const float*)d_in[5];
    const float* b1 = (const float*)d_in[6];
    const float* W2 = (const float*)d_in[7];
    const float* b2 = (const float*)d_in[8];
    const float* W3 = (const float*)d_in[9];
    const float* b3 = (const float*)d_in[10];
    const float* W4 = (const float*)d_in[11];
    const float* b4 = (const float*)d_in[12];

    const int h2 = 256, h1 = 128, h0 = 64;
    int N = in_sizes[0] / h2;                   // 25000
    long long E1 = in_sizes[1] / 2;
    long long E2 = in_sizes[2] / 2;
    long long E3 = in_sizes[3] / 2;
    long long E4 = in_sizes[4] / 2;

    int *cnt, *adj;
    float *dinv, *hraw, *acc4, *p1, *p2;
    cudaGetSymbolAddress((void**)&cnt,  g_cnt);
    cudaGetSymbolAddress((void**)&dinv, g_dinv);
    cudaGetSymbolAddress((void**)&adj,  g_adj);
    cudaGetSymbolAddress((void**)&hraw, g_hraw);
    cudaGetSymbolAddress((void**)&acc4, g_acc4);
    cudaGetSymbolAddress((void**)&p1,   g_p1);
    cudaGetSymbolAddress((void**)&p2,   g_p2);

    // L1: [N, 256] -> [N, 256], relu, no upsample
    gcn_layer_agg(z,  e1,  E1, W1, b1, p1, N,     h2, h2, 0, 1, cnt, dinv, adj, hraw);
    // L2 (upsample x2 folded): [2N] nodes, 256 -> 128, relu
    gcn_layer_agg(p1, ps2, E2, W2, b2, p2, 2 * N, h2, h1, 1, 1, cnt, dinv, adj, hraw);
    // L3: [4N] nodes, 128 -> 64, relu
    gcn_layer_agg(p2, ps1, E3, W3, b3, p1, 4 * N, h1, h0, 1, 1, cnt, dinv, adj, hraw);
    // L4: [8N] nodes, 64 -> 8, no relu, straight to d_out
    gcn_layer4(p1, ps0, E4, W4, b4, (float*)d_out, 8 * N, h0,
               cnt, dinv, hraw, acc4);
}